// round 10
// baseline (speedup 1.0000x reference)
#include <cuda_runtime.h>

// ---------------------------------------------------------------------------
// Fused 2-layer LSTM (H=50, D=1) + FC, B=2048, T=512, fp32.   R10.
//
// thread = (hid-pair hp in [0,25), batch-group bg in [0,7)) -> 175 threads.
// Each thread computes 2 hidden units x 2 batches (register tile): weight
// loads amortized over 2 batches, h loads over 2 hids x 4 gates.
//
//  * Weights: prepacked __device__ global, 16B chunks [kp][chunk][hp] with
//    chunk rows padded to 32 entries (512B) so each warp-LDG touches 1-2
//    lines (L1-resident, sector dedup). LDS gets NO broadcast discount on
//    sm_103a (per-lane-byte crossbar charge) -> weights must NOT be in smem.
//  * h: smem u64 (h_2kp, h_2kp+1) words, row stride 27 u64 (bank-clean).
//  * All dot products: packed fma.rn.f32x2 over k-pairs.
//  * R10 fix vs R9: cell states are proper local arrays c0[2][2]/c1[2][2]
//    indexed only with compile-time-unrolled indices (R9 indexed separate
//    scalars through a pointer -> UB -> rel_err 2e-2).
// ---------------------------------------------------------------------------

#define HN      50
#define KP      25
#define TN      512
#define BATCHN  2048
#define NB      14
#define NHP     25
#define NBG     7
#define NTH     (NHP * NBG)     // 175
#define NGRID   147
#define HS      27              // u64 row stride for h buffers
#define CW      32              // chunk row width (entries, padded 25->32)

typedef unsigned long long u64;

// Prepacked weights (written by prepack_kernel each launch).
// g_w0[(kp*4+c)*CW + hp]: c0 = hid0 gates(i,f) k-pairs, c1 = hid0 (g,o),
//                         c2 = hid1 (i,f),            c3 = hid1 (g,o).
// g_w1[(kp*8+c)*CW + hp]: c0..3 = Wih1 (same pattern), c4..7 = Whh1.
__device__ ulonglong2 g_w0[KP * 4 * CW];    //  51 KB
__device__ ulonglong2 g_w1[KP * 8 * CW];    // 102 KB

__device__ __forceinline__ void fma2(u64& d, u64 a, u64 b) {
    asm("fma.rn.f32x2 %0, %1, %2, %0;" : "+l"(d) : "l"(a), "l"(b));
}
__device__ __forceinline__ float hsum2(u64 v) {
    float lo, hi;
    asm("mov.b64 {%0, %1}, %2;" : "=f"(lo), "=f"(hi) : "l"(v));
    return lo + hi;
}
__device__ __forceinline__ u64 pack2(float lo, float hi) {
    u64 v;
    asm("mov.b64 %0, {%1, %2};" : "=l"(v) : "f"(lo), "f"(hi));
    return v;
}
__device__ __forceinline__ float sig_f(float v) {
    return __fdividef(1.0f, 1.0f + __expf(-v));
}
__device__ __forceinline__ float tanh_f(float v) {
    return 1.0f - __fdividef(2.0f, 1.0f + __expf(2.0f * v));
}

__global__ void prepack_kernel(const float* __restrict__ Whh0,
                               const float* __restrict__ Wih1,
                               const float* __restrict__ Whh1)
{
    const int i = blockIdx.x * blockDim.x + threadIdx.x;
    if (i < KP * 4 * NHP) {
        const int hp = i % NHP, r = i / NHP;
        const int c = r % 4, kp = r / 4;
        const int hid = 2 * hp + (c >> 1);
        const int g0 = (c & 1) * 2, g1 = g0 + 1, k0 = 2 * kp;
        float4 v;
        v.x = Whh0[(g0 * HN + hid) * HN + k0];
        v.y = Whh0[(g0 * HN + hid) * HN + k0 + 1];
        v.z = Whh0[(g1 * HN + hid) * HN + k0];
        v.w = Whh0[(g1 * HN + hid) * HN + k0 + 1];
        reinterpret_cast<float4*>(g_w0)[(kp * 4 + c) * CW + hp] = v;
    }
    if (i < KP * 8 * NHP) {
        const int hp = i % NHP, r = i / NHP;
        const int c = r % 8, kp = r / 8;
        const int mat = c >> 2, sub = c & 3;
        const int hid = 2 * hp + (sub >> 1);
        const int g0 = (sub & 1) * 2, g1 = g0 + 1, k0 = 2 * kp;
        const float* W = mat ? Whh1 : Wih1;
        float4 v;
        v.x = W[(g0 * HN + hid) * HN + k0];
        v.y = W[(g0 * HN + hid) * HN + k0 + 1];
        v.z = W[(g1 * HN + hid) * HN + k0];
        v.w = W[(g1 * HN + hid) * HN + k0 + 1];
        reinterpret_cast<float4*>(g_w1)[(kp * 8 + c) * CW + hp] = v;
    }
}

__global__ __launch_bounds__(NTH, 1)
void lstm_fused_kernel(const float* __restrict__ x,      // [B,T,1]
                       const float* __restrict__ Wih0,   // [200,1]
                       const float* __restrict__ bih0,   // [200]
                       const float* __restrict__ bhh0,   // [200]
                       const float* __restrict__ bih1,   // [200]
                       const float* __restrict__ bhh1,   // [200]
                       const float* __restrict__ Wfc,    // [2,50]
                       const float* __restrict__ bfc,    // [2]
                       float* __restrict__ out)          // [B,2]
{
    __shared__ u64 h0s[2][NB][HS];
    __shared__ u64 h1s[2][NB][HS];
    __shared__ float4 bias0s[HN], bias1s[HN], wx0s[HN];
    __shared__ float wfc_s[2 * HN];
    __shared__ float bfc_s[2];

    const int tid = threadIdx.x;

    // ------- stage biases / x-weights / fc into shared -------
    for (int hid = tid; hid < HN; hid += NTH) {
        bias0s[hid] = make_float4(bih0[0 * HN + hid] + bhh0[0 * HN + hid],
                                  bih0[1 * HN + hid] + bhh0[1 * HN + hid],
                                  bih0[2 * HN + hid] + bhh0[2 * HN + hid],
                                  bih0[3 * HN + hid] + bhh0[3 * HN + hid]);
        bias1s[hid] = make_float4(bih1[0 * HN + hid] + bhh1[0 * HN + hid],
                                  bih1[1 * HN + hid] + bhh1[1 * HN + hid],
                                  bih1[2 * HN + hid] + bhh1[2 * HN + hid],
                                  bih1[3 * HN + hid] + bhh1[3 * HN + hid]);
        wx0s[hid] = make_float4(Wih0[0 * HN + hid], Wih0[1 * HN + hid],
                                Wih0[2 * HN + hid], Wih0[3 * HN + hid]);
    }
    for (int i = tid; i < 2 * HN; i += NTH) wfc_s[i] = Wfc[i];
    if (tid < 2) bfc_s[tid] = bfc[tid];
    for (int i = tid; i < NB * HS; i += NTH) {      // zero buffer 0 (t=0 read)
        (&h0s[0][0][0])[i] = 0ull;
        (&h1s[0][0][0])[i] = 0ull;
    }
    __syncthreads();

    // ------- per-thread identity -------
    const int hp = tid / NBG;           // hid pair: hids 2hp, 2hp+1
    const int bg = tid % NBG;           // batch group: local batches 2bg, 2bg+1
    const int lb0 = 2 * bg, lb1 = lb0 + 1;
    const int hid0 = 2 * hp, hid1 = hid0 + 1;
    const int b0 = blockIdx.x * NB + lb0;
    const int b1 = b0 + 1;
    const long xo0 = (long)(b0 < BATCHN ? b0 : BATCHN - 1) * TN;
    const long xo1 = (long)(b1 < BATCHN ? b1 : BATCHN - 1) * TN;

    const float4 bA0 = bias0s[hid0], bA1 = bias0s[hid1];
    const float4 bB0 = bias1s[hid0], bB1 = bias1s[hid1];
    const float4 wxa = wx0s[hid0],  wxb = wx0s[hid1];

    const ulonglong2* __restrict__ w0p = g_w0 + hp;
    const ulonglong2* __restrict__ w1p = g_w1 + hp;

    // cell states [hid][batch] — REAL arrays, only compile-time indices.
    float c0[2][2], c1[2][2];
#pragma unroll
    for (int h = 0; h < 2; ++h)
#pragma unroll
        for (int b = 0; b < 2; ++b) { c0[h][b] = 0.0f; c1[h][b] = 0.0f; }

    float xa = x[xo0];
    float xb = x[xo1];

#pragma unroll 1
    for (int t = 0; t < TN; ++t) {
        const int rb = t & 1;
        const int wb = rb ^ 1;

        const int tn = (t + 1 < TN) ? (t + 1) : (TN - 1);
        const float xan = x[xo0 + tn];
        const float xbn = x[xo1 + tn];

        // ================= layer 0 =================
        u64 P[2][4][2];
#pragma unroll
        for (int h = 0; h < 2; ++h)
#pragma unroll
            for (int g = 0; g < 4; ++g)
#pragma unroll
                for (int b = 0; b < 2; ++b) P[h][g][b] = 0ull;

#pragma unroll 5
        for (int kp = 0; kp < KP; ++kp) {
            const ulonglong2 wif0 = w0p[(kp * 4 + 0) * CW];  // hid0 (i,f)
            const ulonglong2 wgo0 = w0p[(kp * 4 + 1) * CW];  // hid0 (g,o)
            const ulonglong2 wif1 = w0p[(kp * 4 + 2) * CW];  // hid1 (i,f)
            const ulonglong2 wgo1 = w0p[(kp * 4 + 3) * CW];  // hid1 (g,o)
            const u64 ha = h0s[rb][lb0][kp];
            const u64 hb = h0s[rb][lb1][kp];
            fma2(P[0][0][0], wif0.x, ha); fma2(P[0][1][0], wif0.y, ha);
            fma2(P[0][2][0], wgo0.x, ha); fma2(P[0][3][0], wgo0.y, ha);
            fma2(P[1][0][0], wif1.x, ha); fma2(P[1][1][0], wif1.y, ha);
            fma2(P[1][2][0], wgo1.x, ha); fma2(P[1][3][0], wgo1.y, ha);
            fma2(P[0][0][1], wif0.x, hb); fma2(P[0][1][1], wif0.y, hb);
            fma2(P[0][2][1], wgo0.x, hb); fma2(P[0][3][1], wgo0.y, hb);
            fma2(P[1][0][1], wif1.x, hb); fma2(P[1][1][1], wif1.y, hb);
            fma2(P[1][2][1], wgo1.x, hb); fma2(P[1][3][1], wgo1.y, hb);
        }

        float hv[2][2];   // [hid][batch]
#pragma unroll
        for (int h = 0; h < 2; ++h) {
            const float4 bi = h ? bA1 : bA0;
            const float4 wx = h ? wxb : wxa;
#pragma unroll
            for (int b = 0; b < 2; ++b) {
                const float xv = b ? xb : xa;
                const float Ai = hsum2(P[h][0][b]) + __fmaf_rn(wx.x, xv, bi.x);
                const float Af = hsum2(P[h][1][b]) + __fmaf_rn(wx.y, xv, bi.y);
                const float Ag = hsum2(P[h][2][b]) + __fmaf_rn(wx.z, xv, bi.z);
                const float Ao = hsum2(P[h][3][b]) + __fmaf_rn(wx.w, xv, bi.w);
                const float i_ = sig_f(Ai), f_ = sig_f(Af);
                const float g_ = tanh_f(Ag), o_ = sig_f(Ao);
                c0[h][b] = f_ * c0[h][b] + i_ * g_;
                hv[h][b] = o_ * tanh_f(c0[h][b]);
            }
        }
        h0s[wb][lb0][hp] = pack2(hv[0][0], hv[1][0]);
        h0s[wb][lb1][hp] = pack2(hv[0][1], hv[1][1]);
        __syncthreads();

        // ================= layer 1 =================
        u64 Q[2][4][2];
#pragma unroll
        for (int h = 0; h < 2; ++h)
#pragma unroll
            for (int g = 0; g < 4; ++g)
#pragma unroll
                for (int b = 0; b < 2; ++b) Q[h][g][b] = 0ull;

#pragma unroll 5
        for (int kp = 0; kp < KP; ++kp) {
            const ulonglong2 aif0 = w1p[(kp * 8 + 0) * CW];  // Wih1 hid0 (i,f)
            const ulonglong2 ago0 = w1p[(kp * 8 + 1) * CW];
            const ulonglong2 aif1 = w1p[(kp * 8 + 2) * CW];
            const ulonglong2 ago1 = w1p[(kp * 8 + 3) * CW];
            const ulonglong2 rif0 = w1p[(kp * 8 + 4) * CW];  // Whh1 hid0 (i,f)
            const ulonglong2 rgo0 = w1p[(kp * 8 + 5) * CW];
            const ulonglong2 rif1 = w1p[(kp * 8 + 6) * CW];
            const ulonglong2 rgo1 = w1p[(kp * 8 + 7) * CW];
            const u64 pa = h0s[wb][lb0][kp];   // new h0
            const u64 pb = h0s[wb][lb1][kp];
            const u64 qa = h1s[rb][lb0][kp];   // old h1
            const u64 qb = h1s[rb][lb1][kp];
            fma2(Q[0][0][0], aif0.x, pa); fma2(Q[0][1][0], aif0.y, pa);
            fma2(Q[0][2][0], ago0.x, pa); fma2(Q[0][3][0], ago0.y, pa);
            fma2(Q[1][0][0], aif1.x, pa); fma2(Q[1][1][0], aif1.y, pa);
            fma2(Q[1][2][0], ago1.x, pa); fma2(Q[1][3][0], ago1.y, pa);
            fma2(Q[0][0][0], rif0.x, qa); fma2(Q[0][1][0], rif0.y, qa);
            fma2(Q[0][2][0], rgo0.x, qa); fma2(Q[0][3][0], rgo0.y, qa);
            fma2(Q[1][0][0], rif1.x, qa); fma2(Q[1][1][0], rif1.y, qa);
            fma2(Q[1][2][0], rgo1.x, qa); fma2(Q[1][3][0], rgo1.y, qa);
            fma2(Q[0][0][1], aif0.x, pb); fma2(Q[0][1][1], aif0.y, pb);
            fma2(Q[0][2][1], ago0.x, pb); fma2(Q[0][3][1], ago0.y, pb);
            fma2(Q[1][0][1], aif1.x, pb); fma2(Q[1][1][1], aif1.y, pb);
            fma2(Q[1][2][1], ago1.x, pb); fma2(Q[1][3][1], ago1.y, pb);
            fma2(Q[0][0][1], rif0.x, qb); fma2(Q[0][1][1], rif0.y, qb);
            fma2(Q[0][2][1], rgo0.x, qb); fma2(Q[0][3][1], rgo0.y, qb);
            fma2(Q[1][0][1], rif1.x, qb); fma2(Q[1][1][1], rif1.y, qb);
            fma2(Q[1][2][1], rgo1.x, qb); fma2(Q[1][3][1], rgo1.y, qb);
        }

#pragma unroll
        for (int h = 0; h < 2; ++h) {
            const float4 bi = h ? bB1 : bB0;
#pragma unroll
            for (int b = 0; b < 2; ++b) {
                const float Ai = hsum2(Q[h][0][b]) + bi.x;
                const float Af = hsum2(Q[h][1][b]) + bi.y;
                const float Ag = hsum2(Q[h][2][b]) + bi.z;
                const float Ao = hsum2(Q[h][3][b]) + bi.w;
                const float i_ = sig_f(Ai), f_ = sig_f(Af);
                const float g_ = tanh_f(Ag), o_ = sig_f(Ao);
                c1[h][b] = f_ * c1[h][b] + i_ * g_;
                hv[h][b] = o_ * tanh_f(c1[h][b]);
            }
        }
        h1s[wb][lb0][hp] = pack2(hv[0][0], hv[1][0]);
        h1s[wb][lb1][hp] = pack2(hv[0][1], hv[1][1]);
        __syncthreads();

        xa = xan;
        xb = xbn;
    }

    // ---- final FC: out[b,c] = h1_last[b,:] . Wfc[c,:] + bfc[c] ----
    const int FB = TN & 1;   // buffer holding h1 at t=T-1 (=0 for even T)
    if (tid < NB * 2) {
        const int pb = tid >> 1;
        const int cc = tid & 1;
        const int b = blockIdx.x * NB + pb;
        if (b < BATCHN) {
            float acc = bfc_s[cc];
#pragma unroll
            for (int kp = 0; kp < KP; ++kp) {
                const u64 hpair = h1s[FB][pb][kp];
                float lo, hi;
                asm("mov.b64 {%0, %1}, %2;" : "=f"(lo), "=f"(hi) : "l"(hpair));
                acc += lo * wfc_s[cc * HN + 2 * kp]
                     + hi * wfc_s[cc * HN + 2 * kp + 1];
            }
            out[b * 2 + cc] = acc;
        }
    }
}

extern "C" void kernel_launch(void* const* d_in, const int* in_sizes, int n_in,
                              void* d_out, int out_size)
{
    (void)in_sizes; (void)n_in; (void)out_size;

    const float* x    = (const float*)d_in[0];
    const float* Wih0 = (const float*)d_in[1];
    const float* Whh0 = (const float*)d_in[2];
    const float* bih0 = (const float*)d_in[3];
    const float* bhh0 = (const float*)d_in[4];
    const float* Wih1 = (const float*)d_in[5];
    const float* Whh1 = (const float*)d_in[6];
    const float* bih1 = (const float*)d_in[7];
    const float* bhh1 = (const float*)d_in[8];
    const float* Wfc  = (const float*)d_in[9];
    const float* bfc  = (const float*)d_in[10];

    prepack_kernel<<<(KP * 8 * NHP + 255) / 256, 256>>>(Whh0, Wih1, Whh1);

    lstm_fused_kernel<<<NGRID, NTH>>>(
        x, Wih0, bih0, bhh0, bih1, bhh1, Wfc, bfc, (float*)d_out);
}

// round 11
// speedup vs baseline: 1.0280x; 1.0280x over previous
#include <cuda_runtime.h>

// ---------------------------------------------------------------------------
// Fused 2-layer LSTM (H=50, D=1) + FC, B=2048, T=512, fp32.   R11.
//
// thread = (hid in [0,50), batch-group bg in [0,7)) -> 350 threads, 11 warps.
// Each thread computes 1 hidden unit x 2 batches; cell states in registers.
// (R10's 2-hid x 2-batch tile had the right memory behavior but only 5.5
//  warps/SM -> latency-bound at issue=26%. R11 keeps per-SM totals equal
//  and doubles the warps.)
//
//  * Weights: prepacked __device__ global 16B chunks [kp][chunk][hid], rows
//    padded to 64 entries (1KB) -> a warp (<=5 distinct hids, tid=hid*7+bg)
//    touches an 80B window = 1-2 lines per LDG; L1-resident.
//  * h: smem u64 (h_2kp, h_2kp+1) words, row stride 27 u64 (bank-clean for
//    the 7 even/odd batch rows; writes via float view, 1 rare 2-way STS).
//  * All dot products: packed fma.rn.f32x2 over k-pairs.
// ---------------------------------------------------------------------------

#define HN      50
#define KP      25
#define TN      512
#define BATCHN  2048
#define NB      14
#define NBG     7
#define NTH     (HN * NBG)      // 350
#define NGRID   147
#define HS      27              // u64 row stride for h buffers
#define CW      64              // chunk row width (entries, padded 50->64)

typedef unsigned long long u64;

// Prepacked weights (written by prepack_kernel each launch).
// g_w0[(kp*2+c)*CW + hid]: c0 = gates (i,f) k-pair, c1 = (g,o).     (Whh0)
// g_w1[(kp*4+c)*CW + hid]: c0,1 = Wih1 (i,f),(g,o); c2,3 = Whh1.
__device__ ulonglong2 g_w0[KP * 2 * CW];    //  51 KB
__device__ ulonglong2 g_w1[KP * 4 * CW];    // 102 KB

__device__ __forceinline__ void fma2(u64& d, u64 a, u64 b) {
    asm("fma.rn.f32x2 %0, %1, %2, %0;" : "+l"(d) : "l"(a), "l"(b));
}
__device__ __forceinline__ float hsum2(u64 v) {
    float lo, hi;
    asm("mov.b64 {%0, %1}, %2;" : "=f"(lo), "=f"(hi) : "l"(v));
    return lo + hi;
}
__device__ __forceinline__ float sig_f(float v) {
    return __fdividef(1.0f, 1.0f + __expf(-v));
}
__device__ __forceinline__ float tanh_f(float v) {
    return 1.0f - __fdividef(2.0f, 1.0f + __expf(2.0f * v));
}

__global__ void prepack_kernel(const float* __restrict__ Whh0,
                               const float* __restrict__ Wih1,
                               const float* __restrict__ Whh1)
{
    const int i = blockIdx.x * blockDim.x + threadIdx.x;
    if (i < KP * 2 * HN) {
        const int hid = i % HN, r = i / HN;
        const int c = r % 2, kp = r / 2;
        const int g0 = c * 2, g1 = g0 + 1, k0 = 2 * kp;
        float4 v;
        v.x = Whh0[(g0 * HN + hid) * HN + k0];
        v.y = Whh0[(g0 * HN + hid) * HN + k0 + 1];
        v.z = Whh0[(g1 * HN + hid) * HN + k0];
        v.w = Whh0[(g1 * HN + hid) * HN + k0 + 1];
        reinterpret_cast<float4*>(g_w0)[(kp * 2 + c) * CW + hid] = v;
    }
    if (i < KP * 4 * HN) {
        const int hid = i % HN, r = i / HN;
        const int c = r % 4, kp = r / 4;
        const int mat = c >> 1, sub = c & 1;
        const int g0 = sub * 2, g1 = g0 + 1, k0 = 2 * kp;
        const float* W = mat ? Whh1 : Wih1;
        float4 v;
        v.x = W[(g0 * HN + hid) * HN + k0];
        v.y = W[(g0 * HN + hid) * HN + k0 + 1];
        v.z = W[(g1 * HN + hid) * HN + k0];
        v.w = W[(g1 * HN + hid) * HN + k0 + 1];
        reinterpret_cast<float4*>(g_w1)[(kp * 4 + c) * CW + hid] = v;
    }
}

__global__ __launch_bounds__(NTH, 1)
void lstm_fused_kernel(const float* __restrict__ x,      // [B,T,1]
                       const float* __restrict__ Wih0,   // [200,1]
                       const float* __restrict__ bih0,   // [200]
                       const float* __restrict__ bhh0,   // [200]
                       const float* __restrict__ bih1,   // [200]
                       const float* __restrict__ bhh1,   // [200]
                       const float* __restrict__ Wfc,    // [2,50]
                       const float* __restrict__ bfc,    // [2]
                       float* __restrict__ out)          // [B,2]
{
    __shared__ u64 h0s[2][NB][HS];
    __shared__ u64 h1s[2][NB][HS];
    __shared__ float4 bias0s[HN], bias1s[HN], wx0s[HN];
    __shared__ float wfc_s[2 * HN];
    __shared__ float bfc_s[2];

    const int tid = threadIdx.x;

    // ------- stage biases / x-weights / fc into shared -------
    for (int hid = tid; hid < HN; hid += NTH) {
        bias0s[hid] = make_float4(bih0[0 * HN + hid] + bhh0[0 * HN + hid],
                                  bih0[1 * HN + hid] + bhh0[1 * HN + hid],
                                  bih0[2 * HN + hid] + bhh0[2 * HN + hid],
                                  bih0[3 * HN + hid] + bhh0[3 * HN + hid]);
        bias1s[hid] = make_float4(bih1[0 * HN + hid] + bhh1[0 * HN + hid],
                                  bih1[1 * HN + hid] + bhh1[1 * HN + hid],
                                  bih1[2 * HN + hid] + bhh1[2 * HN + hid],
                                  bih1[3 * HN + hid] + bhh1[3 * HN + hid]);
        wx0s[hid] = make_float4(Wih0[0 * HN + hid], Wih0[1 * HN + hid],
                                Wih0[2 * HN + hid], Wih0[3 * HN + hid]);
    }
    for (int i = tid; i < 2 * HN; i += NTH) wfc_s[i] = Wfc[i];
    if (tid < 2) bfc_s[tid] = bfc[tid];
    for (int i = tid; i < NB * HS; i += NTH) {      // zero buffer 0 (t=0 read)
        (&h0s[0][0][0])[i] = 0ull;
        (&h1s[0][0][0])[i] = 0ull;
    }
    __syncthreads();

    // ------- per-thread identity -------
    const int hid = tid / NBG;          // hidden unit owned by this thread
    const int bg  = tid % NBG;          // local batches 2bg, 2bg+1
    const int lb0 = 2 * bg, lb1 = lb0 + 1;
    const int b0 = blockIdx.x * NB + lb0;
    const int b1 = b0 + 1;
    const long xo0 = (long)(b0 < BATCHN ? b0 : BATCHN - 1) * TN;
    const long xo1 = (long)(b1 < BATCHN ? b1 : BATCHN - 1) * TN;

    const float4 bA = bias0s[hid];
    const float4 bB = bias1s[hid];
    const float4 wx = wx0s[hid];

    const ulonglong2* __restrict__ w0p = g_w0 + hid;
    const ulonglong2* __restrict__ w1p = g_w1 + hid;

    // float views of the h rows this thread writes (one float at [hid])
    float* const h0w0 = reinterpret_cast<float*>(&h0s[0][lb0][0]);
    float* const h0w1 = reinterpret_cast<float*>(&h0s[0][lb1][0]);
    float* const h1w0 = reinterpret_cast<float*>(&h1s[0][lb0][0]);
    float* const h1w1 = reinterpret_cast<float*>(&h1s[0][lb1][0]);
    const int BUFOFF = NB * HS * 2;     // floats per buffer

    float c0a = 0.f, c0b = 0.f;         // layer-0 cell states (2 batches)
    float c1a = 0.f, c1b = 0.f;         // layer-1 cell states

    float xa = x[xo0];
    float xb = x[xo1];

#pragma unroll 1
    for (int t = 0; t < TN; ++t) {
        const int rb = t & 1;
        const int wb = rb ^ 1;

        const int tn = (t + 1 < TN) ? (t + 1) : (TN - 1);
        const float xan = x[xo0 + tn];
        const float xbn = x[xo1 + tn];

        // ================= layer 0 =================
        u64 Pi0 = 0, Pf0 = 0, Pg0 = 0, Po0 = 0;
        u64 Pi1 = 0, Pf1 = 0, Pg1 = 0, Po1 = 0;
#pragma unroll 5
        for (int kp = 0; kp < KP; ++kp) {
            const ulonglong2 wif = w0p[(kp * 2 + 0) * CW];   // (i,f) k-pair
            const ulonglong2 wgo = w0p[(kp * 2 + 1) * CW];   // (g,o)
            const u64 ha = h0s[rb][lb0][kp];
            const u64 hb = h0s[rb][lb1][kp];
            fma2(Pi0, wif.x, ha); fma2(Pf0, wif.y, ha);
            fma2(Pg0, wgo.x, ha); fma2(Po0, wgo.y, ha);
            fma2(Pi1, wif.x, hb); fma2(Pf1, wif.y, hb);
            fma2(Pg1, wgo.x, hb); fma2(Po1, wgo.y, hb);
        }
        float h0a, h0b;
        {
            const float Ai = hsum2(Pi0) + __fmaf_rn(wx.x, xa, bA.x);
            const float Af = hsum2(Pf0) + __fmaf_rn(wx.y, xa, bA.y);
            const float Ag = hsum2(Pg0) + __fmaf_rn(wx.z, xa, bA.z);
            const float Ao = hsum2(Po0) + __fmaf_rn(wx.w, xa, bA.w);
            const float i_ = sig_f(Ai), f_ = sig_f(Af);
            const float g_ = tanh_f(Ag), o_ = sig_f(Ao);
            c0a = f_ * c0a + i_ * g_;
            h0a = o_ * tanh_f(c0a);
        }
        {
            const float Ai = hsum2(Pi1) + __fmaf_rn(wx.x, xb, bA.x);
            const float Af = hsum2(Pf1) + __fmaf_rn(wx.y, xb, bA.y);
            const float Ag = hsum2(Pg1) + __fmaf_rn(wx.z, xb, bA.z);
            const float Ao = hsum2(Po1) + __fmaf_rn(wx.w, xb, bA.w);
            const float i_ = sig_f(Ai), f_ = sig_f(Af);
            const float g_ = tanh_f(Ag), o_ = sig_f(Ao);
            c0b = f_ * c0b + i_ * g_;
            h0b = o_ * tanh_f(c0b);
        }
        h0w0[wb * BUFOFF + hid] = h0a;
        h0w1[wb * BUFOFF + hid] = h0b;
        __syncthreads();

        // ================= layer 1 =================
        u64 Qi0 = 0, Qf0 = 0, Qg0 = 0, Qo0 = 0;
        u64 Qi1 = 0, Qf1 = 0, Qg1 = 0, Qo1 = 0;
#pragma unroll 5
        for (int kp = 0; kp < KP; ++kp) {
            const ulonglong2 aif = w1p[(kp * 4 + 0) * CW];   // Wih1 (i,f)
            const ulonglong2 ago = w1p[(kp * 4 + 1) * CW];   // Wih1 (g,o)
            const ulonglong2 rif = w1p[(kp * 4 + 2) * CW];   // Whh1 (i,f)
            const ulonglong2 rgo = w1p[(kp * 4 + 3) * CW];   // Whh1 (g,o)
            const u64 pa = h0s[wb][lb0][kp];   // new h0
            const u64 pb = h0s[wb][lb1][kp];
            const u64 qa = h1s[rb][lb0][kp];   // old h1
            const u64 qb = h1s[rb][lb1][kp];
            fma2(Qi0, aif.x, pa); fma2(Qf0, aif.y, pa);
            fma2(Qg0, ago.x, pa); fma2(Qo0, ago.y, pa);
            fma2(Qi0, rif.x, qa); fma2(Qf0, rif.y, qa);
            fma2(Qg0, rgo.x, qa); fma2(Qo0, rgo.y, qa);
            fma2(Qi1, aif.x, pb); fma2(Qf1, aif.y, pb);
            fma2(Qg1, ago.x, pb); fma2(Qo1, ago.y, pb);
            fma2(Qi1, rif.x, qb); fma2(Qf1, rif.y, qb);
            fma2(Qg1, rgo.x, qb); fma2(Qo1, rgo.y, qb);
        }
        float h1a, h1b;
        {
            const float Ai = hsum2(Qi0) + bB.x;
            const float Af = hsum2(Qf0) + bB.y;
            const float Ag = hsum2(Qg0) + bB.z;
            const float Ao = hsum2(Qo0) + bB.w;
            const float i_ = sig_f(Ai), f_ = sig_f(Af);
            const float g_ = tanh_f(Ag), o_ = sig_f(Ao);
            c1a = f_ * c1a + i_ * g_;
            h1a = o_ * tanh_f(c1a);
        }
        {
            const float Ai = hsum2(Qi1) + bB.x;
            const float Af = hsum2(Qf1) + bB.y;
            const float Ag = hsum2(Qg1) + bB.z;
            const float Ao = hsum2(Qo1) + bB.w;
            const float i_ = sig_f(Ai), f_ = sig_f(Af);
            const float g_ = tanh_f(Ag), o_ = sig_f(Ao);
            c1b = f_ * c1b + i_ * g_;
            h1b = o_ * tanh_f(c1b);
        }
        h1w0[wb * BUFOFF + hid] = h1a;
        h1w1[wb * BUFOFF + hid] = h1b;
        __syncthreads();

        xa = xan;
        xb = xbn;
    }

    // ---- final FC: out[b,c] = h1_last[b,:] . Wfc[c,:] + bfc[c] ----
    const int FB = TN & 1;   // buffer holding h1 at t=T-1 (=0 for even T)
    if (tid < NB * 2) {
        const int pb = tid >> 1;
        const int cc = tid & 1;
        const int b = blockIdx.x * NB + pb;
        if (b < BATCHN) {
            float acc = bfc_s[cc];
#pragma unroll
            for (int kp = 0; kp < KP; ++kp) {
                const u64 hpair = h1s[FB][pb][kp];
                float lo, hi;
                asm("mov.b64 {%0, %1}, %2;" : "=f"(lo), "=f"(hi) : "l"(hpair));
                acc += lo * wfc_s[cc * HN + 2 * kp]
                     + hi * wfc_s[cc * HN + 2 * kp + 1];
            }
            out[b * 2 + cc] = acc;
        }
    }
}

extern "C" void kernel_launch(void* const* d_in, const int* in_sizes, int n_in,
                              void* d_out, int out_size)
{
    (void)in_sizes; (void)n_in; (void)out_size;

    const float* x    = (const float*)d_in[0];
    const float* Wih0 = (const float*)d_in[1];
    const float* Whh0 = (const float*)d_in[2];
    const float* bih0 = (const float*)d_in[3];
    const float* bhh0 = (const float*)d_in[4];
    const float* Wih1 = (const float*)d_in[5];
    const float* Whh1 = (const float*)d_in[6];
    const float* bih1 = (const float*)d_in[7];
    const float* bhh1 = (const float*)d_in[8];
    const float* Wfc  = (const float*)d_in[9];
    const float* bfc  = (const float*)d_in[10];

    prepack_kernel<<<(KP * 4 * HN + 255) / 256, 256>>>(Whh0, Wih1, Whh1);

    lstm_fused_kernel<<<NGRID, NTH>>>(
        x, Wih0, bih0, bhh0, bih1, bhh1, Wfc, bfc, (float*)d_out);
}